// round 4
// baseline (speedup 1.0000x reference)
#include <cuda_runtime.h>
#include <math_constants.h>

#define NB 4096
#define NC 1000
#define NC4 250
#define NT 9
#define STRIDE 32
#define SMF 56

// Per-sample partials: [0..8]=margin, [9..17]=KD, [18..26]=tgt_logit,
// [27]=CE, [28]=row max over 8 teachers.
__device__ float g_scratch[NB * STRIDE];

__global__ __launch_bounds__(256, 2)
void mt_rows_kernel(const float* __restrict__ p0, const float* __restrict__ p1,
                    const float* __restrict__ p2, const float* __restrict__ p3,
                    const float* __restrict__ p4, const float* __restrict__ p5,
                    const float* __restrict__ p6, const float* __restrict__ p7,
                    const float* __restrict__ ps, const int* __restrict__ ptgt)
{
    const int b    = blockIdx.x;
    const int tid  = threadIdx.x;
    const int lane = tid & 31;
    const int wid  = tid >> 5;

    // Dtype probe: reference asks for int64 targets but JAX-x64-off yields int32.
    // If truly int64 (LE, values<1000), all odd 32-bit words are 0.
    bool is64 = true;
#pragma unroll
    for (int k = 0; k < 16; k++) is64 = is64 && (ptgt[2 * k + 1] == 0);
    const int tgt = is64 ? ptgt[2 * b] : ptgt[b];

    const size_t row = (size_t)b * NC;

    float t1[NT], t2[NT], Zt[NT], At[NT], tl[NT];
#pragma unroll
    for (int t = 0; t < NT; t++) {
        t1[t] = -CUDART_INF_F; t2[t] = -CUDART_INF_F;
        Zt[t] = 0.f; At[t] = 0.f; tl[t] = 0.f;
    }
    float zs1 = 0.f, zs20 = 0.f, tls = 0.f, rmax = -CUDART_INF_F;

    if (tid < NC4) {
        const int c0 = tid * 4;
        float fv[8][4];
        {
            float4 q;
            q = *(const float4*)(p0 + row + c0); fv[0][0]=q.x; fv[0][1]=q.y; fv[0][2]=q.z; fv[0][3]=q.w;
            q = *(const float4*)(p1 + row + c0); fv[1][0]=q.x; fv[1][1]=q.y; fv[1][2]=q.z; fv[1][3]=q.w;
            q = *(const float4*)(p2 + row + c0); fv[2][0]=q.x; fv[2][1]=q.y; fv[2][2]=q.z; fv[2][3]=q.w;
            q = *(const float4*)(p3 + row + c0); fv[3][0]=q.x; fv[3][1]=q.y; fv[3][2]=q.z; fv[3][3]=q.w;
            q = *(const float4*)(p4 + row + c0); fv[4][0]=q.x; fv[4][1]=q.y; fv[4][2]=q.z; fv[4][3]=q.w;
            q = *(const float4*)(p5 + row + c0); fv[5][0]=q.x; fv[5][1]=q.y; fv[5][2]=q.z; fv[5][3]=q.w;
            q = *(const float4*)(p6 + row + c0); fv[6][0]=q.x; fv[6][1]=q.y; fv[6][2]=q.z; fv[6][3]=q.w;
            q = *(const float4*)(p7 + row + c0); fv[7][0]=q.x; fv[7][1]=q.y; fv[7][2]=q.z; fv[7][3]=q.w;
        }
        const float4 qs = *(const float4*)(ps + row + c0);
        const float sv4[4] = {qs.x, qs.y, qs.z, qs.w};

#pragma unroll
        for (int j = 0; j < 4; j++) {
            float mim = ((fv[0][j] + fv[1][j]) + (fv[2][j] + fv[3][j]))
                      + ((fv[4][j] + fv[5][j]) + (fv[6][j] + fv[7][j]));
            mim *= 0.125f;
            const float sv = sv4[j];
            const float lp = sv * 0.05f;          // s / T_KD
            zs1  += __expf(sv);                   // for CE logsumexp
            zs20 += __expf(lp);                   // for KD logsumexp
            const float isT = ((c0 + j) == tgt) ? 1.f : 0.f;
            tls += isT * sv;
#pragma unroll
            for (int t = 0; t < NT; t++) {
                const float v = (t < 8) ? fv[t][j] : mim;
                if (t < 8) rmax = fmaxf(rmax, v);
                const float lo = fminf(t1[t], v);
                t1[t] = fmaxf(t1[t], v);
                t2[t] = fmaxf(t2[t], lo);
                const float e = __expf(v * 0.05f);
                Zt[t] += e;
                At[t] = fmaf(e, lp, At[t]);
                tl[t] += isT * v;
            }
        }
    }

    // intra-warp reduction (all 256 threads participate; idle threads hold identities)
#pragma unroll
    for (int off = 16; off; off >>= 1) {
#pragma unroll
        for (int t = 0; t < NT; t++) {
            const float o1 = __shfl_xor_sync(0xffffffffu, t1[t], off);
            const float o2 = __shfl_xor_sync(0xffffffffu, t2[t], off);
            const float hi = fmaxf(t1[t], o1);
            const float lo = fminf(t1[t], o1);
            t1[t] = hi;
            t2[t] = fmaxf(lo, fmaxf(t2[t], o2));
            Zt[t] += __shfl_xor_sync(0xffffffffu, Zt[t], off);
            At[t] += __shfl_xor_sync(0xffffffffu, At[t], off);
            tl[t] += __shfl_xor_sync(0xffffffffu, tl[t], off);
        }
        zs1  += __shfl_xor_sync(0xffffffffu, zs1, off);
        zs20 += __shfl_xor_sync(0xffffffffu, zs20, off);
        tls  += __shfl_xor_sync(0xffffffffu, tls, off);
        rmax = fmaxf(rmax, __shfl_xor_sync(0xffffffffu, rmax, off));
    }

    __shared__ float sm[8][SMF];
    if (lane == 0) {
#pragma unroll
        for (int t = 0; t < NT; t++) {
            sm[wid][t]      = t1[t];
            sm[wid][9 + t]  = t2[t];
            sm[wid][18 + t] = Zt[t];
            sm[wid][27 + t] = At[t];
            sm[wid][36 + t] = tl[t];
        }
        sm[wid][45] = zs1; sm[wid][46] = zs20; sm[wid][47] = tls; sm[wid][48] = rmax;
    }
    __syncthreads();

    float* out = g_scratch + (size_t)b * STRIDE;
    if (tid < NT) {
        const int t = tid;
        float g1 = -CUDART_INF_F, g2 = -CUDART_INF_F;
        float gZ = 0.f, gA = 0.f, gtl = 0.f, gzs20 = 0.f;
#pragma unroll
        for (int w = 0; w < 8; w++) {
            const float w1 = sm[w][t];
            const float w2 = sm[w][9 + t];
            const float hi = fmaxf(g1, w1);
            const float lo = fminf(g1, w1);
            g1 = hi;
            g2 = fmaxf(lo, fmaxf(g2, w2));
            gZ   += sm[w][18 + t];
            gA   += sm[w][27 + t];
            gtl  += sm[w][36 + t];
            gzs20 += sm[w][46];
        }
        const float lse20 = __logf(gzs20);                 // log Σ exp(s/20)
        const float kd = 400.f * (lse20 - gA / gZ);        // T_KD^2 * KD cross-entropy
        const float margin = (gtl == g1) ? (g1 - g2) : 0.f;
        out[t]      = margin;
        out[9 + t]  = kd;
        out[18 + t] = gtl;
    } else if (tid == NT) {
        float gzs1 = 0.f, gtls = 0.f, grm = -CUDART_INF_F;
#pragma unroll
        for (int w = 0; w < 8; w++) {
            gzs1 += sm[w][45];
            gtls += sm[w][47];
            grm = fmaxf(grm, sm[w][48]);
        }
        out[27] = __logf(gzs1) - gtls;   // CE = logsumexp(s) - s[tgt]
        out[28] = grm;
    }
}

__global__ __launch_bounds__(1024)
void mt_final_kernel(float* __restrict__ dout)
{
    const int tid  = threadIdx.x;
    const int lane = tid & 31;
    const int wid  = tid >> 5;
    __shared__ float sred[32];
    __shared__ float sM;

    // phase 1: global max over 8 teachers (max_preds)
    float m = -CUDART_INF_F;
    for (int b = tid; b < NB; b += 1024)
        m = fmaxf(m, g_scratch[(size_t)b * STRIDE + 28]);
#pragma unroll
    for (int off = 16; off; off >>= 1)
        m = fmaxf(m, __shfl_xor_sync(0xffffffffu, m, off));
    if (lane == 0) sred[wid] = m;
    __syncthreads();
    if (wid == 0) {
        float v = sred[lane];
#pragma unroll
        for (int off = 16; off; off >>= 1)
            v = fmaxf(v, __shfl_xor_sync(0xffffffffu, v, off));
        if (lane == 0) sM = v;
    }
    __syncthreads();
    const float invM = 1.f / sM;

    // phase 2: threshold softmax + dynamic-weighted loss, mean over samples
    float acc = 0.f;
    for (int b = tid; b < NB; b += 1024) {
        const float* o = g_scratch + (size_t)b * STRIDE;
        const float CE = o[27];
        float th[NT];
        float se = 0.f;
#pragma unroll
        for (int t = 0; t < NT; t++) {
            th[t] = __expf(o[t] * 0.5f);   // margin / T_THR
            se += th[t];
        }
        float num = 0.f;
#pragma unroll
        for (int t = 0; t < NT; t++) {
            const float w  = o[18 + t] * invM;
            const float aw = 0.8f * w;
            const float loss = (1.f - aw) * CE + aw * o[9 + t];
            num = fmaf(th[t], loss, num);
        }
        acc += num / se;
    }
#pragma unroll
    for (int off = 16; off; off >>= 1)
        acc += __shfl_xor_sync(0xffffffffu, acc, off);
    __syncthreads();
    if (lane == 0) sred[wid] = acc;
    __syncthreads();
    if (tid == 0) {
        float s = 0.f;
#pragma unroll
        for (int w = 0; w < 32; w++) s += sred[w];
        dout[0] = s * (1.f / NB);
    }
}

extern "C" void kernel_launch(void* const* d_in, const int* in_sizes, int n_in,
                              void* d_out, int out_size)
{
    (void)in_sizes; (void)n_in; (void)out_size;
    mt_rows_kernel<<<NB, 256>>>(
        (const float*)d_in[0], (const float*)d_in[1],
        (const float*)d_in[2], (const float*)d_in[3],
        (const float*)d_in[4], (const float*)d_in[5],
        (const float*)d_in[6], (const float*)d_in[7],
        (const float*)d_in[8], (const int*)d_in[9]);
    mt_final_kernel<<<1, 1024>>>((float*)d_out);
}

// round 5
// speedup vs baseline: 2.0550x; 2.0550x over previous
#include <cuda_runtime.h>
#include <math_constants.h>

#define NB 4096
#define NC 1000
#define NC4 250
#define NT 9

#define LOG2E  1.4426950408889634f
#define LN2    0.6931471805599453f
#define C20K   0.07213475204444817f   /* 0.05 * log2(e) */
#define CTHR   0.7213475204444817f    /* 0.5  * log2(e) */

// SoA per-sample partials (coalesced for the final reduce)
__device__ float g_A[NB];   // CE
__device__ float g_B[NB];   // sum_t thr_t * tgtl_t * (KD_t - CE)
__device__ float g_R[NB];   // row max over 8 teachers

__device__ __forceinline__ float ex2f(float x) {
    float r; asm("ex2.approx.ftz.f32 %0, %1;" : "=f"(r) : "f"(x)); return r;
}
__device__ __forceinline__ float lg2f(float x) {
    float r; asm("lg2.approx.ftz.f32 %0, %1;" : "=f"(r) : "f"(x)); return r;
}

__global__ __launch_bounds__(256, 2)
void mt_rows_kernel(const float* __restrict__ p0, const float* __restrict__ p1,
                    const float* __restrict__ p2, const float* __restrict__ p3,
                    const float* __restrict__ p4, const float* __restrict__ p5,
                    const float* __restrict__ p6, const float* __restrict__ p7,
                    const float* __restrict__ ps, const int* __restrict__ ptgt)
{
    const int b    = blockIdx.x;
    const int tid  = threadIdx.x;
    const int lane = tid & 31;
    const int wid  = tid >> 5;

    // Dtype probe: reference declares int64 targets; JAX-x64-off materializes int32.
    bool is64 = true;
#pragma unroll
    for (int k = 0; k < 16; k++) is64 = is64 && (ptgt[2 * k + 1] == 0);
    const int tgt = is64 ? ptgt[2 * b] : ptgt[b];

    const size_t row = (size_t)b * NC;

    __shared__ float sm[8][40];
    __shared__ float s_tl[NT];
    __shared__ float s_tls;

    float t1[NT], t2[NT], Zt[NT], At[NT];
#pragma unroll
    for (int t = 0; t < NT; t++) {
        t1[t] = -CUDART_INF_F; t2[t] = -CUDART_INF_F;
        Zt[t] = 0.f; At[t] = 0.f;
    }
    float zs1 = 0.f, zs20 = 0.f;

    if (tid < NC4) {
        const int c0 = tid * 4;
        float fv[8][4];
        {
            float4 q;
            q = *(const float4*)(p0 + row + c0); fv[0][0]=q.x; fv[0][1]=q.y; fv[0][2]=q.z; fv[0][3]=q.w;
            q = *(const float4*)(p1 + row + c0); fv[1][0]=q.x; fv[1][1]=q.y; fv[1][2]=q.z; fv[1][3]=q.w;
            q = *(const float4*)(p2 + row + c0); fv[2][0]=q.x; fv[2][1]=q.y; fv[2][2]=q.z; fv[2][3]=q.w;
            q = *(const float4*)(p3 + row + c0); fv[3][0]=q.x; fv[3][1]=q.y; fv[3][2]=q.z; fv[3][3]=q.w;
            q = *(const float4*)(p4 + row + c0); fv[4][0]=q.x; fv[4][1]=q.y; fv[4][2]=q.z; fv[4][3]=q.w;
            q = *(const float4*)(p5 + row + c0); fv[5][0]=q.x; fv[5][1]=q.y; fv[5][2]=q.z; fv[5][3]=q.w;
            q = *(const float4*)(p6 + row + c0); fv[6][0]=q.x; fv[6][1]=q.y; fv[6][2]=q.z; fv[6][3]=q.w;
            q = *(const float4*)(p7 + row + c0); fv[7][0]=q.x; fv[7][1]=q.y; fv[7][2]=q.z; fv[7][3]=q.w;
        }
        const float4 qs = *(const float4*)(ps + row + c0);
        const float sv4[4] = {qs.x, qs.y, qs.z, qs.w};

#pragma unroll
        for (int j = 0; j < 4; j++) {
            float mim = ((fv[0][j] + fv[1][j]) + (fv[2][j] + fv[3][j]))
                      + ((fv[4][j] + fv[5][j]) + (fv[6][j] + fv[7][j]));
            mim *= 0.125f;
            const float sv = sv4[j];
            zs1  += ex2f(sv * LOG2E);
            zs20 += ex2f(sv * C20K);
            if ((c0 + j) == tgt) {
                s_tls  = sv;
                s_tl[8] = mim;
#pragma unroll
                for (int t = 0; t < 8; t++) s_tl[t] = fv[t][j];
            }
#pragma unroll
            for (int t = 0; t < NT; t++) {
                const float v = (t < 8) ? fv[t][j] : mim;
                const float lo = fminf(t1[t], v);
                t1[t] = fmaxf(t1[t], v);
                t2[t] = fmaxf(t2[t], lo);
                const float e = ex2f(v * C20K);
                Zt[t] += e;
                At[t] = fmaf(e, v, At[t]);     // accumulates e*v; scaled by 0.05 at the end
            }
        }
    }

    // intra-warp reduction
#pragma unroll
    for (int off = 16; off; off >>= 1) {
#pragma unroll
        for (int t = 0; t < NT; t++) {
            const float o1 = __shfl_xor_sync(0xffffffffu, t1[t], off);
            const float o2 = __shfl_xor_sync(0xffffffffu, t2[t], off);
            const float hi = fmaxf(t1[t], o1);
            const float lo = fminf(t1[t], o1);
            t1[t] = hi;
            t2[t] = fmaxf(lo, fmaxf(t2[t], o2));
            Zt[t] += __shfl_xor_sync(0xffffffffu, Zt[t], off);
            At[t] += __shfl_xor_sync(0xffffffffu, At[t], off);
        }
        zs1  += __shfl_xor_sync(0xffffffffu, zs1, off);
        zs20 += __shfl_xor_sync(0xffffffffu, zs20, off);
    }

    if (lane == 0) {
#pragma unroll
        for (int t = 0; t < NT; t++) {
            sm[wid][t]      = t1[t];
            sm[wid][9 + t]  = t2[t];
            sm[wid][18 + t] = Zt[t];
            sm[wid][27 + t] = At[t];
        }
        sm[wid][36] = zs1;
        sm[wid][37] = zs20;
    }
    __syncthreads();

    // warp 0: cross-warp combine + per-sample epilogue (thr softmax folded in)
    if (wid == 0) {
        const int t = lane;
        float e = 0.f, contrib = 0.f, rmaxv = -CUDART_INF_F, CE = 0.f;
        if (t < NT) {
            float g1 = -CUDART_INF_F, g2 = -CUDART_INF_F;
            float gZ = 0.f, gA = 0.f, gz1 = 0.f, gz20 = 0.f;
#pragma unroll
            for (int w = 0; w < 8; w++) {
                const float w1 = sm[w][t];
                const float w2 = sm[w][9 + t];
                const float hi = fmaxf(g1, w1);
                const float lo = fminf(g1, w1);
                g1 = hi;
                g2 = fmaxf(lo, fmaxf(g2, w2));
                gZ   += sm[w][18 + t];
                gA   += sm[w][27 + t];
                gz1  += sm[w][36];
                gz20 += sm[w][37];
            }
            CE = lg2f(gz1) * LN2 - s_tls;                       // logsumexp(s) - s_tgt
            const float lse20 = lg2f(gz20) * LN2;               // log sum exp(s/20)
            const float kd = 400.f * (lse20 - (gA / gZ) * 0.05f);
            const float tgl = s_tl[t];
            const float margin = (tgl == g1) ? (g1 - g2) : 0.f;
            e = ex2f(margin * CTHR);                            // exp(margin/2)
            contrib = e * tgl * (kd - CE);
            if (t < 8) rmaxv = g1;                              // mimic excluded from max_preds
        }
        float se = e, nm = contrib, rm = rmaxv;
#pragma unroll
        for (int off = 16; off; off >>= 1) {
            se += __shfl_xor_sync(0xffffffffu, se, off);
            nm += __shfl_xor_sync(0xffffffffu, nm, off);
            rm = fmaxf(rm, __shfl_xor_sync(0xffffffffu, rm, off));
        }
        if (lane == 0) {
            g_A[b] = CE;
            g_B[b] = nm / se;
            g_R[b] = rm;
        }
    }
}

__global__ __launch_bounds__(1024)
void mt_final_kernel(float* __restrict__ dout)
{
    const int tid  = threadIdx.x;
    const int lane = tid & 31;
    const int wid  = tid >> 5;
    __shared__ float sA[32], sB[32], sR[32];

    float a = 0.f, bb = 0.f, r = -CUDART_INF_F;
#pragma unroll
    for (int k = 0; k < NB / 1024; k++) {
        const int i = tid + k * 1024;
        a  += g_A[i];
        bb += g_B[i];
        r = fmaxf(r, g_R[i]);
    }
#pragma unroll
    for (int off = 16; off; off >>= 1) {
        a  += __shfl_xor_sync(0xffffffffu, a, off);
        bb += __shfl_xor_sync(0xffffffffu, bb, off);
        r = fmaxf(r, __shfl_xor_sync(0xffffffffu, r, off));
    }
    if (lane == 0) { sA[wid] = a; sB[wid] = bb; sR[wid] = r; }
    __syncthreads();
    if (tid == 0) {
        float ta = 0.f, tb = 0.f, tr = -CUDART_INF_F;
#pragma unroll
        for (int w = 0; w < 32; w++) {
            ta += sA[w]; tb += sB[w]; tr = fmaxf(tr, sR[w]);
        }
        dout[0] = ta * (1.f / NB) + 0.8f * tb / (tr * NB);
    }
}

extern "C" void kernel_launch(void* const* d_in, const int* in_sizes, int n_in,
                              void* d_out, int out_size)
{
    (void)in_sizes; (void)n_in; (void)out_size;
    mt_rows_kernel<<<NB, 256>>>(
        (const float*)d_in[0], (const float*)d_in[1],
        (const float*)d_in[2], (const float*)d_in[3],
        (const float*)d_in[4], (const float*)d_in[5],
        (const float*)d_in[6], (const float*)d_in[7],
        (const float*)d_in[8], (const int*)d_in[9]);
    mt_final_kernel<<<1, 1024>>>((float*)d_out);
}